// round 13
// baseline (speedup 1.0000x reference)
#include <cuda_runtime.h>
#include <math.h>

// Problem shape: B=32768, T=512, channels=3, C=128 logits.
#define T_LEN 512
#define LOSS_SCALE 4194304.0f    // 2^22 fixed point => deterministic loss sum

__device__ unsigned long long g_loss_acc = 0ULL;
__device__ int                g_score_acc = 0;
__device__ unsigned int       g_done = 0u;

__global__ __launch_bounds__(128) void fused_kernel(
    const float* __restrict__ imu,
    const float* __restrict__ preds,
    const int*   __restrict__ labels_w,   // raw 32-bit view of labels buffer
    float*       __restrict__ out,
    int B)
{
    // Tiny shared: warp-boundary stash + reduction scratch (~1.1 KB total).
    __shared__ float stash[4][4][4][3];   // [ownerWarp][ownerLane<4][k][c]
    __shared__ float redf[7][4];
    __shared__ int   redi[2][4];
    __shared__ float lsh[4];

    const int tid  = threadIdx.x;
    const int warp = tid >> 5;
    const int lane = tid & 31;
    const unsigned FULL = 0xffffffffu;

    if ((int)blockIdx.x < B) {
        // ============ PHYSICS: one CTA per window, stride-128 ownership ======
        // Thread tid owns timesteps t_k = tid + 128k, k=0..3.
        const int b = blockIdx.x;
        const float* wbase = imu + (size_t)b * (T_LEN * 3) + 3 * tid;

        // 12 independent scalar LDG (coalesced: warp spans 384B per instr).
        float a[4][3];
#pragma unroll
        for (int k = 0; k < 4; k++)
#pragma unroll
            for (int c = 0; c < 3; c++)
                a[k][c] = wbase[384 * k + c];

        // Publish boundary values (lanes 0..3 of each warp) for cross-warp halo.
        if (lane < 4) {
#pragma unroll
            for (int k = 0; k < 4; k++)
#pragma unroll
                for (int c = 0; c < 3; c++)
                    stash[warp][lane][k][c] = a[k][c];
        }
        __syncthreads();

        // ---- Pass A: sums, sum-of-squares, max|w| (mean-independent) ----
        float s0 = 0.f, s1 = 0.f, s2 = 0.f, q = 0.f;
        float M0 = 0.f, M1 = 0.f, M2 = 0.f;
#pragma unroll
        for (int k = 0; k < 4; k++) {
            float w0 = a[k][0], w1 = a[k][1], w2 = a[k][2];
            s0 += w0; s1 += w1; s2 += w2;
            q = fmaf(w0, w0, q); q = fmaf(w1, w1, q); q = fmaf(w2, w2, q);
            M0 = fmaxf(M0, fabsf(w0));
            M1 = fmaxf(M1, fabsf(w1));
            M2 = fmaxf(M2, fabsf(w2));
        }

        // ---- Jerk counts (mean-independent) + zc neighbor capture ----
        // |jerk|>5000  <=>  |w[t] - 2w[t+2] + w[t+4]| > 8,  valid t < 508.
        int jc = 0;
        float n1[4];   // w0[t+1] for zc (compared after mean is known)
#pragma unroll
        for (int k = 0; k < 4; k++) {
            float b2[3], b4[3];
#pragma unroll
            for (int c = 0; c < 3; c++) {
                float v = __shfl_down_sync(FULL, a[k][c], 2);
                if (lane >= 30) {               // t+2 owner in next warp
                    int t2 = tid + 2;
                    int kk = k + (t2 >= 128); kk = kk > 3 ? 3 : kk;
                    t2 &= 127;
                    v = stash[t2 >> 5][t2 & 31][kk][c];
                }
                b2[c] = v;
            }
#pragma unroll
            for (int c = 0; c < 3; c++) {
                // lanes 28,29 get t+4 via lane+2's patched b2; 30,31 via stash.
                float v = __shfl_down_sync(FULL, b2[c], 2);
                if (lane >= 30) {
                    int t4 = tid + 4;
                    int kk = k + (t4 >= 128); kk = kk > 3 ? 3 : kk;
                    t4 &= 127;
                    v = stash[t4 >> 5][t4 & 31][kk][c];
                }
                b4[c] = v;
            }
            if (k < 3 || tid < 124) {           // t = tid+128k < 508
#pragma unroll
                for (int c = 0; c < 3; c++) {
                    float jv = fmaf(-2.0f, b2[c], a[k][c] + b4[c]);
                    jc += (fabsf(jv) > 8.0f);
                }
            }
            // w0[t+1]
            float v1 = __shfl_down_sync(FULL, a[k][0], 1);
            if (lane == 31) {
                int t1 = tid + 1;
                int kk = k + (t1 >= 128); kk = kk > 3 ? 3 : kk;
                t1 &= 127;
                v1 = stash[t1 >> 5][t1 & 31][kk][0];
            }
            n1[k] = v1;
        }

        // ---- Warp reduce 7 floats, then CTA combine ----
#pragma unroll
        for (int o = 16; o; o >>= 1) {
            s0 += __shfl_xor_sync(FULL, s0, o);
            s1 += __shfl_xor_sync(FULL, s1, o);
            s2 += __shfl_xor_sync(FULL, s2, o);
            q  += __shfl_xor_sync(FULL, q, o);
            M0 = fmaxf(M0, __shfl_xor_sync(FULL, M0, o));
            M1 = fmaxf(M1, __shfl_xor_sync(FULL, M1, o));
            M2 = fmaxf(M2, __shfl_xor_sync(FULL, M2, o));
        }
        if (lane == 0) {
            redf[0][warp] = s0; redf[1][warp] = s1; redf[2][warp] = s2;
            redf[3][warp] = q;
            redf[4][warp] = M0; redf[5][warp] = M1; redf[6][warp] = M2;
        }
        __syncthreads();
        const float m0 = (redf[0][0] + redf[0][1] + redf[0][2] + redf[0][3]) * (1.0f / 512.0f);
        const float m1 = (redf[1][0] + redf[1][1] + redf[1][2] + redf[1][3]) * (1.0f / 512.0f);
        const float m2 = (redf[2][0] + redf[2][1] + redf[2][2] + redf[2][3]) * (1.0f / 512.0f);
        const float qT =  redf[3][0] + redf[3][1] + redf[3][2] + redf[3][3];
        const float X0 = fmaxf(fmaxf(redf[4][0], redf[4][1]), fmaxf(redf[4][2], redf[4][3]));
        const float X1 = fmaxf(fmaxf(redf[5][0], redf[5][1]), fmaxf(redf[5][2], redf[5][3]));
        const float X2 = fmaxf(fmaxf(redf[6][0], redf[6][1]), fmaxf(redf[6][2], redf[6][3]));
        const float tv = qT * (1.0f / 512.0f) - (m0 * m0 + m1 * m1 + m2 * m2);

        // ---- Pass B: zc (needs mean) + at_max (rare; data still in regs) ----
        int zc = 0;
#pragma unroll
        for (int k = 0; k < 4; k++) {
            if (k < 3 || tid < 127) {           // t < 511
                float d0 = a[k][0] - m0;
                float e0 = n1[k] - m0;
                zc += (d0 * e0 < 0.0f);
            }
        }
        int c0 = 0, c1 = 0, c2 = 0;
        const bool needAM = (X0 >= 0.5f) || (X1 >= 0.5f) || (X2 >= 0.5f);
        if (needAM) {                           // CTA-uniform, ~0.1% of windows
#pragma unroll
            for (int k = 0; k < 4; k++) {
                c0 += (fabsf(fabsf(a[k][0]) - X0) < 0.01f);
                c1 += (fabsf(fabsf(a[k][1]) - X1) < 0.01f);
                c2 += (fabsf(fabsf(a[k][2]) - X2) < 0.01f);
            }
        }
        int pa = c0 | (c1 << 10) | (c2 << 20);  // counts <= 512 each
        int pb = zc | (jc << 16);               // zc <= 511, jc <= 1524
#pragma unroll
        for (int o = 16; o; o >>= 1) {
            pa += __shfl_xor_sync(FULL, pa, o);
            pb += __shfl_xor_sync(FULL, pb, o);
        }
        if (lane == 0) { redi[0][warp] = pa; redi[1][warp] = pb; }
        __syncthreads();

        if (tid == 0) {
            int paT = redi[0][0] + redi[0][1] + redi[0][2] + redi[0][3];
            int pbT = redi[1][0] + redi[1][1] + redi[1][2] + redi[1][3];
            int cc0 = paT & 1023, cc1 = (paT >> 10) & 1023, cc2 = (paT >> 20) & 1023;
            int zcc = pbT & 0xffff, jcc = pbT >> 16;

            bool reject = tv < 0.005f;
            reject |= (X0 >= 0.5f) && ((float)cc0 * (1.0f / 512.0f) > 0.2f);
            reject |= (X1 >= 0.5f) && ((float)cc1 * (1.0f / 512.0f) > 0.2f);
            reject |= (X2 >= 0.5f) && ((float)cc2 * (1.0f / 512.0f) > 0.2f);
            reject |= (jcc >= 77);              // js[1447]>5000 <=> count >= 77

            float s1v = tv > 10.0f ? 90.0f
                      : (tv > 2.0f ? 80.0f : (tv > 0.5f ? 70.0f : 58.0f));
            float zcr = (float)zcc * (1.0f / 512.0f);
            float s2v = zcr > 0.15f ? 85.0f : (zcr > 0.07f ? 70.0f : 55.0f);
            int score = (int)floorf((s1v + s2v) * 0.5f);
            if (!reject) atomicAdd(&g_score_acc, score);
        }
    } else {
        // ============ TASK LOSS: one row per warp, 4 rows/CTA ============
        const int row = ((int)blockIdx.x - B) * 4 + warp;

        // Labels dtype detect (first 128 words; L2-hit after first CTA):
        // int64 LE => all odd words (high halves of values < 128) are zero.
        int aa = labels_w[2 * lane + 1] | labels_w[2 * (lane + 32) + 1];
#pragma unroll
        for (int o = 16; o; o >>= 1) aa |= __shfl_xor_sync(FULL, aa, o);
        const int is64 = (aa == 0);

        if (row < B) {
            const float4* p4 =
                reinterpret_cast<const float4*>(preds + (size_t)row * 128);
            float4 vv = p4[lane];
            float mx = fmaxf(fmaxf(vv.x, vv.y), fmaxf(vv.z, vv.w));
#pragma unroll
            for (int o = 16; o; o >>= 1) mx = fmaxf(mx, __shfl_xor_sync(FULL, mx, o));
            float sum = __expf(vv.x - mx) + __expf(vv.y - mx) +
                        __expf(vv.z - mx) + __expf(vv.w - mx);
#pragma unroll
            for (int o = 16; o; o >>= 1) sum += __shfl_xor_sync(FULL, sum, o);
            if (lane == 0) {
                int lbl = is64 ? labels_w[2 * (size_t)row] : labels_w[row];
                float pl = preds[(size_t)row * 128 + lbl];
                lsh[warp] = __logf(sum) + mx - pl;   // -(pl - logsumexp)
            }
        } else if (lane == 0) {
            lsh[warp] = 0.f;
        }
        __syncthreads();
        if (tid == 0) {
            unsigned long long acc = 0ULL;
#pragma unroll
            for (int j = 0; j < 4; j++)
                acc += (unsigned long long)llrintf(lsh[j] * LOSS_SCALE);
            atomicAdd(&g_loss_acc, acc);
        }
    }

    // ============ Last-CTA finalize (deterministic: integer sums) ============
    if (tid == 0) {
        __threadfence();
        unsigned int done = atomicAdd(&g_done, 1u);
        if (done == gridDim.x - 1) {
            unsigned long long L = atomicAdd(&g_loss_acc, 0ULL);
            int S = atomicAdd(&g_score_acc, 0);
            double task = (double)L / ((double)LOSS_SCALE * (double)B);
            double pen  = 1.0 - (double)S / (100.0 * (double)B);
            out[0] = (float)(task + 0.3 * pen);
            // Reset so the captured graph replays identically.
            atomicExch(&g_loss_acc, 0ULL);
            atomicExch(&g_score_acc, 0);
            __threadfence();
            atomicExch(&g_done, 0u);
        }
    }
}

// ---------------------------------------------------------------------------
extern "C" void kernel_launch(void* const* d_in, const int* in_sizes, int n_in,
                              void* d_out, int out_size) {
    const float* preds    = (const float*)d_in[0];
    const int*   labels_w = (const int*)d_in[1];
    const float* imu      = (const float*)d_in[2];
    const int B = in_sizes[1];                  // 32768

    const int taskCtas = (B + 3) / 4;           // 8192
    fused_kernel<<<B + taskCtas, 128>>>(imu, preds, labels_w, (float*)d_out, B);
}

// round 14
// speedup vs baseline: 1.2222x; 1.2222x over previous
#include <cuda_runtime.h>
#include <math.h>

// Problem shape: B=32768, T=512, channels=3, C=128 logits.
#define T_LEN 512
#define WIN_BYTES (T_LEN * 3 * 4)       // 6144, multiple of 16
#define LOSS_SCALE 4194304.0f           // 2^22 fixed point => deterministic sum

__device__ unsigned long long g_loss_acc = 0ULL;
__device__ int                g_score_acc = 0;
__device__ unsigned int       g_done = 0u;

__device__ __forceinline__ unsigned smem_u32(const void* p) {
    unsigned r;
    asm("{ .reg .u64 t; cvta.to.shared.u64 t, %1; cvt.u32.u64 %0, t; }"
        : "=r"(r) : "l"(p));
    return r;
}

__global__ __launch_bounds__(128) void fused_kernel(
    const float* __restrict__ imu,
    const float* __restrict__ preds,
    const int*   __restrict__ labels_w,   // raw 32-bit view of labels buffer
    float*       __restrict__ out,
    int B)
{
    // 6KB window (TMA dst, 16B aligned) + pad so tid=127 halo LDS stays in-bounds.
    __shared__ __align__(16) float s[T_LEN * 3 + 48];
    __shared__ unsigned long long mbar;
    __shared__ float redf[7][4];
    __shared__ int   redi[2][4];
    __shared__ float lsh[4];

    const int tid  = threadIdx.x;
    const int warp = tid >> 5;
    const int lane = tid & 31;
    const unsigned FULL = 0xffffffffu;

    if ((int)blockIdx.x < B) {
        // ========== PHYSICS: one CTA per window, TMA bulk staging ==========
        const int b = blockIdx.x;
        const unsigned mb   = smem_u32(&mbar);
        const unsigned sdst = smem_u32(s);

        if (tid == 0)
            asm volatile("mbarrier.init.shared.b64 [%0], 1;" :: "r"(mb) : "memory");
        __syncthreads();
        if (tid == 0) {
            const float* src = imu + (size_t)b * (T_LEN * 3);
            asm volatile("mbarrier.arrive.expect_tx.shared.b64 _, [%0], %1;"
                         :: "r"(mb), "r"((unsigned)WIN_BYTES) : "memory");
            asm volatile(
                "cp.async.bulk.shared::cluster.global.mbarrier::complete_tx::bytes"
                " [%0], [%1], %2, [%3];"
                :: "r"(sdst), "l"(src), "r"((unsigned)WIN_BYTES), "r"(mb)
                : "memory");
        }
        // All threads wait for the 6KB to land (parity 0).
        asm volatile(
            "{\n\t.reg .pred P;\n\t"
            "W%=:\n\t"
            "mbarrier.try_wait.parity.acquire.cta.shared::cta.b64 P, [%0], 0, 0x989680;\n\t"
            "@P bra D%=;\n\t"
            "bra W%=;\n\t"
            "D%=:\n\t}"
            :: "r"(mb) : "memory");

        // Own timesteps 4*tid..4*tid+3 (+4 halo) = 6 conflict-free LDS.128.
        float f[24];
        {
            const float4* sv = reinterpret_cast<const float4*>(s + 12 * tid);
#pragma unroll
            for (int j = 0; j < 6; j++)
                *reinterpret_cast<float4*>(f + 4 * j) = sv[j];
        }

        // ---- Pass 1: per-channel sum, sum-of-squares, max|w| ----
        float s0 = 0.f, s1 = 0.f, s2 = 0.f, q = 0.f;
        float M0 = 0.f, M1 = 0.f, M2 = 0.f;
#pragma unroll
        for (int i = 0; i < 4; i++) {
            float w0 = f[3 * i], w1 = f[3 * i + 1], w2 = f[3 * i + 2];
            s0 += w0; s1 += w1; s2 += w2;
            q = fmaf(w0, w0, q); q = fmaf(w1, w1, q); q = fmaf(w2, w2, q);
            M0 = fmaxf(M0, fabsf(w0));
            M1 = fmaxf(M1, fabsf(w1));
            M2 = fmaxf(M2, fabsf(w2));
        }
#pragma unroll
        for (int o = 16; o; o >>= 1) {
            s0 += __shfl_xor_sync(FULL, s0, o);
            s1 += __shfl_xor_sync(FULL, s1, o);
            s2 += __shfl_xor_sync(FULL, s2, o);
            q  += __shfl_xor_sync(FULL, q, o);
        }
        // abs-values >= 0: float order == uint order -> hardware warp reduce.
        M0 = __uint_as_float(__reduce_max_sync(FULL, __float_as_uint(M0)));
        M1 = __uint_as_float(__reduce_max_sync(FULL, __float_as_uint(M1)));
        M2 = __uint_as_float(__reduce_max_sync(FULL, __float_as_uint(M2)));

        if (lane == 0) {
            redf[0][warp] = s0; redf[1][warp] = s1; redf[2][warp] = s2;
            redf[3][warp] = q;
            redf[4][warp] = M0; redf[5][warp] = M1; redf[6][warp] = M2;
        }
        __syncthreads();
        const float m0 = (redf[0][0] + redf[0][1] + redf[0][2] + redf[0][3]) * (1.0f / 512.0f);
        const float m1 = (redf[1][0] + redf[1][1] + redf[1][2] + redf[1][3]) * (1.0f / 512.0f);
        const float m2 = (redf[2][0] + redf[2][1] + redf[2][2] + redf[2][3]) * (1.0f / 512.0f);
        const float qT =  redf[3][0] + redf[3][1] + redf[3][2] + redf[3][3];
        const float X0 = fmaxf(fmaxf(redf[4][0], redf[4][1]), fmaxf(redf[4][2], redf[4][3]));
        const float X1 = fmaxf(fmaxf(redf[5][0], redf[5][1]), fmaxf(redf[5][2], redf[5][3]));
        const float X2 = fmaxf(fmaxf(redf[6][0], redf[6][1]), fmaxf(redf[6][2], redf[6][3]));
        // tv = sum(w^2)/n - sum_c m_c^2 ; n*m^2 << sum w^2, no cancellation risk.
        const float tv = qT * (1.0f / 512.0f) - (m0 * m0 + m1 * m1 + m2 * m2);

        // ---- Pass 2: zc, jerk, (rare) at_max — all register-resident ----
        int zc = 0, jc = 0, c0 = 0, c1 = 0, c2 = 0;
        const bool notLast = (tid != 127);
#pragma unroll
        for (int i = 0; i < 4; i++) {
            // zero crossings, channel 0: pair (t, t+1), t < 511
            if (notLast || i < 3) {
                float d0 = f[3 * i] - m0;
                float e0 = f[3 * i + 3] - m0;    // i==3 -> f[12] = halo
                zc += (d0 * e0 < 0.0f);
            }
            // |jerk|>5000 <=> |w[t] - 2w[t+2] + w[t+4]| > 8, valid t < 508
            if (notLast) {
#pragma unroll
                for (int c = 0; c < 3; c++) {
                    float a  = f[3 * i + c];
                    float bb = f[3 * (i + 2) + c];
                    float cc = f[3 * (i + 4) + c];
                    float jv = fmaf(-2.0f, bb, a + cc);
                    jc += (fabsf(jv) > 8.0f);
                }
            }
        }
        const bool needAM = (X0 >= 0.5f) || (X1 >= 0.5f) || (X2 >= 0.5f);
        if (needAM) {                        // CTA-uniform, ~0.1% of windows
#pragma unroll
            for (int i = 0; i < 4; i++) {
                c0 += (fabsf(fabsf(f[3 * i])     - X0) < 0.01f);
                c1 += (fabsf(fabsf(f[3 * i + 1]) - X1) < 0.01f);
                c2 += (fabsf(fabsf(f[3 * i + 2]) - X2) < 0.01f);
            }
        }
        // Pack: c* <= 512 (10 bits); zc <= 511, jc <= 1524.
        int pa = c0 | (c1 << 10) | (c2 << 20);
        int pb = zc | (jc << 16);
        pa = (int)__reduce_add_sync(FULL, (unsigned)pa);
        pb = (int)__reduce_add_sync(FULL, (unsigned)pb);
        if (lane == 0) { redi[0][warp] = pa; redi[1][warp] = pb; }
        __syncthreads();

        if (tid == 0) {
            int paT = redi[0][0] + redi[0][1] + redi[0][2] + redi[0][3];
            int pbT = redi[1][0] + redi[1][1] + redi[1][2] + redi[1][3];
            int cc0 = paT & 1023, cc1 = (paT >> 10) & 1023, cc2 = (paT >> 20) & 1023;
            int zcc = pbT & 0xffff, jcc = pbT >> 16;

            bool reject = tv < 0.005f;
            reject |= (X0 >= 0.5f) && ((float)cc0 * (1.0f / 512.0f) > 0.2f);
            reject |= (X1 >= 0.5f) && ((float)cc1 * (1.0f / 512.0f) > 0.2f);
            reject |= (X2 >= 0.5f) && ((float)cc2 * (1.0f / 512.0f) > 0.2f);
            reject |= (jcc >= 77);           // js[1447]>5000 <=> count >= 77

            float s1v = tv > 10.0f ? 90.0f
                      : (tv > 2.0f ? 80.0f : (tv > 0.5f ? 70.0f : 58.0f));
            float zcr = (float)zcc * (1.0f / 512.0f);
            float s2v = zcr > 0.15f ? 85.0f : (zcr > 0.07f ? 70.0f : 55.0f);
            int score = (int)floorf((s1v + s2v) * 0.5f);
            if (!reject) atomicAdd(&g_score_acc, score);
        }
    } else {
        // ============ TASK LOSS: one row per warp, 4 rows/CTA ============
        const int row = ((int)blockIdx.x - B) * 4 + warp;

        // Labels dtype detect (first 128 words; L2-hit after first CTA):
        // int64 LE => all odd words (high halves of values < 128) are zero.
        int aa = labels_w[2 * lane + 1] | labels_w[2 * (lane + 32) + 1];
        aa = (int)__reduce_add_sync(FULL, (unsigned)aa);  // nonzero iff any set
        const int is64 = (aa == 0);

        if (row < B) {
            const float4* p4 =
                reinterpret_cast<const float4*>(preds + (size_t)row * 128);
            float4 vv = p4[lane];
            float mx = fmaxf(fmaxf(vv.x, vv.y), fmaxf(vv.z, vv.w));
#pragma unroll
            for (int o = 16; o; o >>= 1) mx = fmaxf(mx, __shfl_xor_sync(FULL, mx, o));
            float sum = __expf(vv.x - mx) + __expf(vv.y - mx) +
                        __expf(vv.z - mx) + __expf(vv.w - mx);
#pragma unroll
            for (int o = 16; o; o >>= 1) sum += __shfl_xor_sync(FULL, sum, o);
            if (lane == 0) {
                int lbl = is64 ? labels_w[2 * (size_t)row] : labels_w[row];
                float pl = preds[(size_t)row * 128 + lbl];
                lsh[warp] = __logf(sum) + mx - pl;   // -(pl - logsumexp)
            }
        } else if (lane == 0) {
            lsh[warp] = 0.f;
        }
        __syncthreads();
        if (tid == 0) {
            unsigned long long acc = 0ULL;
#pragma unroll
            for (int j = 0; j < 4; j++)
                acc += (unsigned long long)llrintf(lsh[j] * LOSS_SCALE);
            atomicAdd(&g_loss_acc, acc);
        }
    }

    // ============ Last-CTA finalize (deterministic: integer sums) ============
    if (tid == 0) {
        __threadfence();
        unsigned int done = atomicAdd(&g_done, 1u);
        if (done == gridDim.x - 1) {
            unsigned long long L = atomicAdd(&g_loss_acc, 0ULL);
            int S = atomicAdd(&g_score_acc, 0);
            double task = (double)L / ((double)LOSS_SCALE * (double)B);
            double pen  = 1.0 - (double)S / (100.0 * (double)B);
            out[0] = (float)(task + 0.3 * pen);
            // Reset so the captured graph replays identically.
            atomicExch(&g_loss_acc, 0ULL);
            atomicExch(&g_score_acc, 0);
            __threadfence();
            atomicExch(&g_done, 0u);
        }
    }
}

// ---------------------------------------------------------------------------
extern "C" void kernel_launch(void* const* d_in, const int* in_sizes, int n_in,
                              void* d_out, int out_size) {
    const float* preds    = (const float*)d_in[0];
    const int*   labels_w = (const int*)d_in[1];
    const float* imu      = (const float*)d_in[2];
    const int B = in_sizes[1];                  // 32768

    const int taskCtas = (B + 3) / 4;           // 8192
    fused_kernel<<<B + taskCtas, 128>>>(imu, preds, labels_w, (float*)d_out, B);
}

// round 15
// speedup vs baseline: 1.2287x; 1.0053x over previous
#include <cuda_runtime.h>
#include <math.h>

// Problem shape: B=32768, T=512, channels=3, C=128 logits.
#define T_LEN 512
#define WIN_BYTES (T_LEN * 3 * 4)       // 6144, multiple of 16
#define LOSS_SCALE 4194304.0f           // 2^22 fixed point => deterministic sum

__device__ unsigned long long g_loss_acc = 0ULL;
__device__ int                g_score_acc = 0;
__device__ unsigned int       g_done = 0u;

__device__ __forceinline__ unsigned smem_u32(const void* p) {
    unsigned r;
    asm("{ .reg .u64 t; cvta.to.shared.u64 t, %1; cvt.u32.u64 %0, t; }"
        : "=r"(r) : "l"(p));
    return r;
}

__global__ __launch_bounds__(128) void fused_kernel(
    const float* __restrict__ imu,
    const float* __restrict__ preds,
    const int*   __restrict__ labels_w,   // raw 32-bit view of labels buffer
    float*       __restrict__ out,
    int B)
{
    // 6KB window (TMA dst, 16B aligned) + pad so tid=127 halo LDS stays in-bounds.
    __shared__ __align__(16) float s[T_LEN * 3 + 48];
    __shared__ unsigned long long mbar;
    __shared__ float redf[7][4];
    __shared__ int   redi[2][4];
    __shared__ float lsh[4];

    const int tid  = threadIdx.x;
    const int warp = tid >> 5;
    const int lane = tid & 31;
    const unsigned FULL = 0xffffffffu;

    if ((int)blockIdx.x < B) {
        // ========== PHYSICS: one CTA per window, TMA bulk staging ==========
        const int b = blockIdx.x;
        const unsigned mb   = smem_u32(&mbar);
        const unsigned sdst = smem_u32(s);

        if (tid == 0)
            asm volatile("mbarrier.init.shared.b64 [%0], 1;" :: "r"(mb) : "memory");
        __syncthreads();
        if (tid == 0) {
            const float* src = imu + (size_t)b * (T_LEN * 3);
            asm volatile("mbarrier.arrive.expect_tx.shared.b64 _, [%0], %1;"
                         :: "r"(mb), "r"((unsigned)WIN_BYTES) : "memory");
            asm volatile(
                "cp.async.bulk.shared::cluster.global.mbarrier::complete_tx::bytes"
                " [%0], [%1], %2, [%3];"
                :: "r"(sdst), "l"(src), "r"((unsigned)WIN_BYTES), "r"(mb)
                : "memory");
        }
        // All threads wait for the 6KB to land (parity 0).
        asm volatile(
            "{\n\t.reg .pred P;\n\t"
            "W%=:\n\t"
            "mbarrier.try_wait.parity.acquire.cta.shared::cta.b64 P, [%0], 0, 0x989680;\n\t"
            "@P bra D%=;\n\t"
            "bra W%=;\n\t"
            "D%=:\n\t}"
            :: "r"(mb) : "memory");

        // Own timesteps 4*tid..4*tid+3 (+4 halo) = 6 conflict-free LDS.128.
        float f[24];
        {
            const float4* sv = reinterpret_cast<const float4*>(s + 12 * tid);
#pragma unroll
            for (int j = 0; j < 6; j++)
                *reinterpret_cast<float4*>(f + 4 * j) = sv[j];
        }

        // ---- Pass 1: per-channel sum, sum-of-squares, max|w| ----
        float s0 = 0.f, s1 = 0.f, s2 = 0.f, q = 0.f;
        float M0 = 0.f, M1 = 0.f, M2 = 0.f;
#pragma unroll
        for (int i = 0; i < 4; i++) {
            float w0 = f[3 * i], w1 = f[3 * i + 1], w2 = f[3 * i + 2];
            s0 += w0; s1 += w1; s2 += w2;
            q = fmaf(w0, w0, q); q = fmaf(w1, w1, q); q = fmaf(w2, w2, q);
            M0 = fmaxf(M0, fabsf(w0));
            M1 = fmaxf(M1, fabsf(w1));
            M2 = fmaxf(M2, fabsf(w2));
        }
#pragma unroll
        for (int o = 16; o; o >>= 1) {
            s0 += __shfl_xor_sync(FULL, s0, o);
            s1 += __shfl_xor_sync(FULL, s1, o);
            s2 += __shfl_xor_sync(FULL, s2, o);
            q  += __shfl_xor_sync(FULL, q, o);
        }
        // abs-values >= 0: float order == uint order -> hardware warp reduce.
        M0 = __uint_as_float(__reduce_max_sync(FULL, __float_as_uint(M0)));
        M1 = __uint_as_float(__reduce_max_sync(FULL, __float_as_uint(M1)));
        M2 = __uint_as_float(__reduce_max_sync(FULL, __float_as_uint(M2)));

        if (lane == 0) {
            redf[0][warp] = s0; redf[1][warp] = s1; redf[2][warp] = s2;
            redf[3][warp] = q;
            redf[4][warp] = M0; redf[5][warp] = M1; redf[6][warp] = M2;
        }
        __syncthreads();
        const float m0 = (redf[0][0] + redf[0][1] + redf[0][2] + redf[0][3]) * (1.0f / 512.0f);
        const float m1 = (redf[1][0] + redf[1][1] + redf[1][2] + redf[1][3]) * (1.0f / 512.0f);
        const float m2 = (redf[2][0] + redf[2][1] + redf[2][2] + redf[2][3]) * (1.0f / 512.0f);
        const float qT =  redf[3][0] + redf[3][1] + redf[3][2] + redf[3][3];
        const float X0 = fmaxf(fmaxf(redf[4][0], redf[4][1]), fmaxf(redf[4][2], redf[4][3]));
        const float X1 = fmaxf(fmaxf(redf[5][0], redf[5][1]), fmaxf(redf[5][2], redf[5][3]));
        const float X2 = fmaxf(fmaxf(redf[6][0], redf[6][1]), fmaxf(redf[6][2], redf[6][3]));
        // tv = sum(w^2)/n - sum_c m_c^2 ; n*m^2 << sum w^2, no cancellation risk.
        const float tv = qT * (1.0f / 512.0f) - (m0 * m0 + m1 * m1 + m2 * m2);

        // ---- Pass 2: zc, jerk, (rare) at_max — all register-resident ----
        int zc = 0, jc = 0, c0 = 0, c1 = 0, c2 = 0;
        const bool notLast = (tid != 127);
#pragma unroll
        for (int i = 0; i < 4; i++) {
            // zero crossings, channel 0: pair (t, t+1), t < 511
            if (notLast || i < 3) {
                float d0 = f[3 * i] - m0;
                float e0 = f[3 * i + 3] - m0;    // i==3 -> f[12] = halo
                zc += (d0 * e0 < 0.0f);
            }
            // |jerk|>5000 <=> |w[t] - 2w[t+2] + w[t+4]| > 8, valid t < 508
            if (notLast) {
#pragma unroll
                for (int c = 0; c < 3; c++) {
                    float a  = f[3 * i + c];
                    float bb = f[3 * (i + 2) + c];
                    float cc = f[3 * (i + 4) + c];
                    float jv = fmaf(-2.0f, bb, a + cc);
                    jc += (fabsf(jv) > 8.0f);
                }
            }
        }
        const bool needAM = (X0 >= 0.5f) || (X1 >= 0.5f) || (X2 >= 0.5f);
        if (needAM) {                        // CTA-uniform, ~0.1% of windows
#pragma unroll
            for (int i = 0; i < 4; i++) {
                c0 += (fabsf(fabsf(f[3 * i])     - X0) < 0.01f);
                c1 += (fabsf(fabsf(f[3 * i + 1]) - X1) < 0.01f);
                c2 += (fabsf(fabsf(f[3 * i + 2]) - X2) < 0.01f);
            }
        }
        // Pack: c* <= 512 (10 bits); zc <= 511, jc <= 1524.
        int pa = c0 | (c1 << 10) | (c2 << 20);
        int pb = zc | (jc << 16);
        pa = (int)__reduce_add_sync(FULL, (unsigned)pa);
        pb = (int)__reduce_add_sync(FULL, (unsigned)pb);
        if (lane == 0) { redi[0][warp] = pa; redi[1][warp] = pb; }
        __syncthreads();

        if (tid == 0) {
            int paT = redi[0][0] + redi[0][1] + redi[0][2] + redi[0][3];
            int pbT = redi[1][0] + redi[1][1] + redi[1][2] + redi[1][3];
            int cc0 = paT & 1023, cc1 = (paT >> 10) & 1023, cc2 = (paT >> 20) & 1023;
            int zcc = pbT & 0xffff, jcc = pbT >> 16;

            bool reject = tv < 0.005f;
            reject |= (X0 >= 0.5f) && ((float)cc0 * (1.0f / 512.0f) > 0.2f);
            reject |= (X1 >= 0.5f) && ((float)cc1 * (1.0f / 512.0f) > 0.2f);
            reject |= (X2 >= 0.5f) && ((float)cc2 * (1.0f / 512.0f) > 0.2f);
            reject |= (jcc >= 77);           // js[1447]>5000 <=> count >= 77

            float s1v = tv > 10.0f ? 90.0f
                      : (tv > 2.0f ? 80.0f : (tv > 0.5f ? 70.0f : 58.0f));
            float zcr = (float)zcc * (1.0f / 512.0f);
            float s2v = zcr > 0.15f ? 85.0f : (zcr > 0.07f ? 70.0f : 55.0f);
            int score = (int)floorf((s1v + s2v) * 0.5f);
            if (!reject) atomicAdd(&g_score_acc, score);
        }
    } else {
        // ============ TASK LOSS: one row per warp, 4 rows/CTA ============
        const int row = ((int)blockIdx.x - B) * 4 + warp;

        // Labels dtype detect (first 128 words; L2-hit after first CTA):
        // int64 LE => all odd words (high halves of values < 128) are zero.
        int aa = labels_w[2 * lane + 1] | labels_w[2 * (lane + 32) + 1];
        aa = (int)__reduce_add_sync(FULL, (unsigned)aa);  // nonzero iff any set
        const int is64 = (aa == 0);

        if (row < B) {
            const float4* p4 =
                reinterpret_cast<const float4*>(preds + (size_t)row * 128);
            float4 vv = p4[lane];
            float mx = fmaxf(fmaxf(vv.x, vv.y), fmaxf(vv.z, vv.w));
#pragma unroll
            for (int o = 16; o; o >>= 1) mx = fmaxf(mx, __shfl_xor_sync(FULL, mx, o));
            float sum = __expf(vv.x - mx) + __expf(vv.y - mx) +
                        __expf(vv.z - mx) + __expf(vv.w - mx);
#pragma unroll
            for (int o = 16; o; o >>= 1) sum += __shfl_xor_sync(FULL, sum, o);
            if (lane == 0) {
                int lbl = is64 ? labels_w[2 * (size_t)row] : labels_w[row];
                float pl = preds[(size_t)row * 128 + lbl];
                lsh[warp] = __logf(sum) + mx - pl;   // -(pl - logsumexp)
            }
        } else if (lane == 0) {
            lsh[warp] = 0.f;
        }
        __syncthreads();
        if (tid == 0) {
            unsigned long long acc = 0ULL;
#pragma unroll
            for (int j = 0; j < 4; j++)
                acc += (unsigned long long)llrintf(lsh[j] * LOSS_SCALE);
            atomicAdd(&g_loss_acc, acc);
        }
    }

    // ============ Last-CTA finalize (deterministic: integer sums) ============
    if (tid == 0) {
        __threadfence();
        unsigned int done = atomicAdd(&g_done, 1u);
        if (done == gridDim.x - 1) {
            unsigned long long L = atomicAdd(&g_loss_acc, 0ULL);
            int S = atomicAdd(&g_score_acc, 0);
            double task = (double)L / ((double)LOSS_SCALE * (double)B);
            double pen  = 1.0 - (double)S / (100.0 * (double)B);
            out[0] = (float)(task + 0.3 * pen);
            // Reset so the captured graph replays identically.
            atomicExch(&g_loss_acc, 0ULL);
            atomicExch(&g_score_acc, 0);
            __threadfence();
            atomicExch(&g_done, 0u);
        }
    }
}

// ---------------------------------------------------------------------------
extern "C" void kernel_launch(void* const* d_in, const int* in_sizes, int n_in,
                              void* d_out, int out_size) {
    const float* preds    = (const float*)d_in[0];
    const int*   labels_w = (const int*)d_in[1];
    const float* imu      = (const float*)d_in[2];
    const int B = in_sizes[1];                  // 32768

    const int taskCtas = (B + 3) / 4;           // 8192
    fused_kernel<<<B + taskCtas, 128>>>(imu, preds, labels_w, (float*)d_out, B);
}

// round 16
// speedup vs baseline: 1.5372x; 1.2511x over previous
#include <cuda_runtime.h>
#include <math.h>

// Problem shape: B=32768, T=512, channels=3, C=128 logits.
#define T_LEN 512
#define WIN_BYTES (T_LEN * 3 * 4)       // 6144
#define NW 8                            // windows per physics CTA
#define STG_FLTS (T_LEN * 3 + 16)       // stage stride (floats), 16B-multiple, halo pad
#define LOSS_SCALE 4194304.0f           // 2^22 fixed point => deterministic sum

__device__ unsigned long long g_loss_acc = 0ULL;
__device__ int                g_score_acc = 0;
__device__ unsigned int       g_done = 0u;

__device__ __forceinline__ unsigned smem_u32(const void* p) {
    unsigned r;
    asm("{ .reg .u64 t; cvta.to.shared.u64 t, %1; cvt.u32.u64 %0, t; }"
        : "=r"(r) : "l"(p));
    return r;
}

__device__ __forceinline__ void tma_issue(unsigned mb, unsigned sdst, const float* src) {
    asm volatile("mbarrier.arrive.expect_tx.shared.b64 _, [%0], %1;"
                 :: "r"(mb), "r"((unsigned)WIN_BYTES) : "memory");
    asm volatile(
        "cp.async.bulk.shared::cluster.global.mbarrier::complete_tx::bytes"
        " [%0], [%1], %2, [%3];"
        :: "r"(sdst), "l"(src), "r"((unsigned)WIN_BYTES), "r"(mb) : "memory");
}

__device__ __forceinline__ void mbar_wait(unsigned mb, unsigned ph) {
    asm volatile(
        "{\n\t.reg .pred P;\n\t"
        "W%=:\n\t"
        "mbarrier.try_wait.parity.acquire.cta.shared::cta.b64 P, [%0], %1, 0x989680;\n\t"
        "@P bra D%=;\n\t"
        "bra W%=;\n\t"
        "D%=:\n\t}"
        :: "r"(mb), "r"(ph) : "memory");
}

__global__ __launch_bounds__(128) void fused_kernel(
    const float* __restrict__ imu,
    const float* __restrict__ preds,
    const int*   __restrict__ labels_w,   // raw 32-bit view of labels buffer
    float*       __restrict__ out,
    int B, int physCtas)
{
    // Two 6.2KB TMA stages + reduction scratch.
    __shared__ __align__(16) float sbuf[2][STG_FLTS];
    __shared__ __align__(8) unsigned long long mbar[2];
    __shared__ float redf[7][4];
    __shared__ int   redi[2][4];
    __shared__ float lsh[4];

    const int tid  = threadIdx.x;
    const int warp = tid >> 5;
    const int lane = tid & 31;
    const unsigned FULL = 0xffffffffu;

    if ((int)blockIdx.x < physCtas) {
        // ===== PHYSICS: NW windows per CTA, double-buffered TMA pipeline =====
        const int b0 = blockIdx.x * NW;
        const unsigned mb0 = smem_u32(&mbar[0]);
        const unsigned mb1 = smem_u32(&mbar[1]);
        const unsigned sd0 = smem_u32(sbuf[0]);
        const unsigned sd1 = smem_u32(sbuf[1]);
        const float* gsrc = imu + (size_t)b0 * (T_LEN * 3);

        if (tid == 0) {
            asm volatile("mbarrier.init.shared.b64 [%0], 1;" :: "r"(mb0) : "memory");
            asm volatile("mbarrier.init.shared.b64 [%0], 1;" :: "r"(mb1) : "memory");
        }
        __syncthreads();
        if (tid == 0) {
            tma_issue(mb0, sd0, gsrc);                    // window 0
            tma_issue(mb1, sd1, gsrc + T_LEN * 3);        // window 1
        }

        int scoreSum = 0;   // meaningful on tid 0 only

#pragma unroll 1
        for (int w = 0; w < NW; w++) {
            const int stage = w & 1;
            const unsigned mb = stage ? mb1 : mb0;
            const unsigned ph = (w >> 1) & 1;
            mbar_wait(mb, ph);

            // Own timesteps 4*tid..4*tid+3 (+4 halo): 6 conflict-free LDS.128.
            float f[24];
            {
                const float4* sv =
                    reinterpret_cast<const float4*>(sbuf[stage] + 12 * tid);
#pragma unroll
                for (int j = 0; j < 6; j++)
                    *reinterpret_cast<float4*>(f + 4 * j) = sv[j];
            }
            __syncthreads();   // buffer fully consumed -> safe to refill
            if (tid == 0 && w + 2 < NW)
                tma_issue(mb, stage ? sd1 : sd0, gsrc + (size_t)(w + 2) * (T_LEN * 3));

            // ---- Pass 1: per-channel sum, sum-of-squares, max|w| ----
            float s0 = 0.f, s1 = 0.f, s2 = 0.f, q = 0.f;
            float M0 = 0.f, M1 = 0.f, M2 = 0.f;
#pragma unroll
            for (int i = 0; i < 4; i++) {
                float w0 = f[3 * i], w1 = f[3 * i + 1], w2 = f[3 * i + 2];
                s0 += w0; s1 += w1; s2 += w2;
                q = fmaf(w0, w0, q); q = fmaf(w1, w1, q); q = fmaf(w2, w2, q);
                M0 = fmaxf(M0, fabsf(w0));
                M1 = fmaxf(M1, fabsf(w1));
                M2 = fmaxf(M2, fabsf(w2));
            }
#pragma unroll
            for (int o = 16; o; o >>= 1) {
                s0 += __shfl_xor_sync(FULL, s0, o);
                s1 += __shfl_xor_sync(FULL, s1, o);
                s2 += __shfl_xor_sync(FULL, s2, o);
                q  += __shfl_xor_sync(FULL, q, o);
            }
            // abs-values >= 0: float order == uint order -> HW warp reduce.
            M0 = __uint_as_float(__reduce_max_sync(FULL, __float_as_uint(M0)));
            M1 = __uint_as_float(__reduce_max_sync(FULL, __float_as_uint(M1)));
            M2 = __uint_as_float(__reduce_max_sync(FULL, __float_as_uint(M2)));

            if (lane == 0) {
                redf[0][warp] = s0; redf[1][warp] = s1; redf[2][warp] = s2;
                redf[3][warp] = q;
                redf[4][warp] = M0; redf[5][warp] = M1; redf[6][warp] = M2;
            }
            __syncthreads();
            const float m0 = (redf[0][0] + redf[0][1] + redf[0][2] + redf[0][3]) * (1.0f / 512.0f);
            const float m1 = (redf[1][0] + redf[1][1] + redf[1][2] + redf[1][3]) * (1.0f / 512.0f);
            const float m2 = (redf[2][0] + redf[2][1] + redf[2][2] + redf[2][3]) * (1.0f / 512.0f);
            const float qT =  redf[3][0] + redf[3][1] + redf[3][2] + redf[3][3];
            const float X0 = fmaxf(fmaxf(redf[4][0], redf[4][1]), fmaxf(redf[4][2], redf[4][3]));
            const float X1 = fmaxf(fmaxf(redf[5][0], redf[5][1]), fmaxf(redf[5][2], redf[5][3]));
            const float X2 = fmaxf(fmaxf(redf[6][0], redf[6][1]), fmaxf(redf[6][2], redf[6][3]));
            // tv = sum(w^2)/n - sum_c m_c^2 (n*m^2 << sum w^2: no cancellation).
            const float tv = qT * (1.0f / 512.0f) - (m0 * m0 + m1 * m1 + m2 * m2);

            // ---- Pass 2: zc, jerk, (rare) at_max — register-resident ----
            int zc = 0, jc = 0, c0 = 0, c1 = 0, c2 = 0;
            const bool notLast = (tid != 127);
#pragma unroll
            for (int i = 0; i < 4; i++) {
                if (notLast || i < 3) {               // zc pairs t < 511
                    float d0 = f[3 * i] - m0;
                    float e0 = f[3 * i + 3] - m0;     // i==3 -> halo
                    zc += (d0 * e0 < 0.0f);
                }
                if (notLast) {                        // jerk t < 508
#pragma unroll
                    for (int c = 0; c < 3; c++) {
                        float a  = f[3 * i + c];
                        float bb = f[3 * (i + 2) + c];
                        float cc = f[3 * (i + 4) + c];
                        float jv = fmaf(-2.0f, bb, a + cc);
                        jc += (fabsf(jv) > 8.0f);     // == |jerk| > 5000
                    }
                }
            }
            const bool needAM = (X0 >= 0.5f) || (X1 >= 0.5f) || (X2 >= 0.5f);
            if (needAM) {                             // CTA-uniform, ~0.1%
#pragma unroll
                for (int i = 0; i < 4; i++) {
                    c0 += (fabsf(fabsf(f[3 * i])     - X0) < 0.01f);
                    c1 += (fabsf(fabsf(f[3 * i + 1]) - X1) < 0.01f);
                    c2 += (fabsf(fabsf(f[3 * i + 2]) - X2) < 0.01f);
                }
            }
            int pa = c0 | (c1 << 10) | (c2 << 20);    // counts <= 512 each
            int pb = zc | (jc << 16);                 // zc <= 511, jc <= 1524
            pa = (int)__reduce_add_sync(FULL, (unsigned)pa);
            pb = (int)__reduce_add_sync(FULL, (unsigned)pb);
            if (lane == 0) { redi[0][warp] = pa; redi[1][warp] = pb; }
            __syncthreads();

            if (tid == 0) {
                int paT = redi[0][0] + redi[0][1] + redi[0][2] + redi[0][3];
                int pbT = redi[1][0] + redi[1][1] + redi[1][2] + redi[1][3];
                int cc0 = paT & 1023, cc1 = (paT >> 10) & 1023, cc2 = (paT >> 20) & 1023;
                int zcc = pbT & 0xffff, jcc = pbT >> 16;

                bool reject = tv < 0.005f;
                reject |= (X0 >= 0.5f) && ((float)cc0 * (1.0f / 512.0f) > 0.2f);
                reject |= (X1 >= 0.5f) && ((float)cc1 * (1.0f / 512.0f) > 0.2f);
                reject |= (X2 >= 0.5f) && ((float)cc2 * (1.0f / 512.0f) > 0.2f);
                reject |= (jcc >= 77);    // js[1447]>5000 <=> count >= 77

                float s1v = tv > 10.0f ? 90.0f
                          : (tv > 2.0f ? 80.0f : (tv > 0.5f ? 70.0f : 58.0f));
                float zcr = (float)zcc * (1.0f / 512.0f);
                float s2v = zcr > 0.15f ? 85.0f : (zcr > 0.07f ? 70.0f : 55.0f);
                if (!reject) scoreSum += (int)floorf((s1v + s2v) * 0.5f);
            }
            __syncthreads();   // redi/redf reads done before next iteration
        }
        if (tid == 0 && scoreSum) atomicAdd(&g_score_acc, scoreSum);
    } else {
        // ============ TASK LOSS: 2 rows per warp, 8 rows/CTA ============
        const int base = ((int)blockIdx.x - physCtas) * 8 + warp;

        // Labels dtype detect (first 128 words; L2-hit after first CTA):
        // int64 LE => all odd words (high halves of values < 128) are zero.
        int aa = labels_w[2 * lane + 1] | labels_w[2 * (lane + 32) + 1];
        aa = (int)__reduce_add_sync(FULL, (unsigned)aa);
        const int is64 = (aa == 0);

        float lossSum = 0.f;
#pragma unroll
        for (int r = 0; r < 2; r++) {
            const int row = base + 4 * r;
            if (row < B) {
                const float4* p4 =
                    reinterpret_cast<const float4*>(preds + (size_t)row * 128);
                float4 vv = p4[lane];
                float mx = fmaxf(fmaxf(vv.x, vv.y), fmaxf(vv.z, vv.w));
#pragma unroll
                for (int o = 16; o; o >>= 1)
                    mx = fmaxf(mx, __shfl_xor_sync(FULL, mx, o));
                float sum = __expf(vv.x - mx) + __expf(vv.y - mx) +
                            __expf(vv.z - mx) + __expf(vv.w - mx);
#pragma unroll
                for (int o = 16; o; o >>= 1)
                    sum += __shfl_xor_sync(FULL, sum, o);
                if (lane == 0) {
                    int lbl = is64 ? labels_w[2 * (size_t)row] : labels_w[row];
                    float pl = preds[(size_t)row * 128 + lbl];
                    lossSum += __logf(sum) + mx - pl;   // -(pl - logsumexp)
                }
            }
        }
        if (lane == 0) lsh[warp] = lossSum;
        __syncthreads();
        if (tid == 0) {
            unsigned long long acc = 0ULL;
#pragma unroll
            for (int j = 0; j < 4; j++)
                acc += (unsigned long long)llrintf(lsh[j] * LOSS_SCALE);
            atomicAdd(&g_loss_acc, acc);
        }
    }

    // ============ Last-CTA finalize (deterministic: integer sums) ============
    if (tid == 0) {
        __threadfence();
        unsigned int done = atomicAdd(&g_done, 1u);
        if (done == gridDim.x - 1) {
            unsigned long long L = atomicAdd(&g_loss_acc, 0ULL);
            int S = atomicAdd(&g_score_acc, 0);
            double task = (double)L / ((double)LOSS_SCALE * (double)B);
            double pen  = 1.0 - (double)S / (100.0 * (double)B);
            out[0] = (float)(task + 0.3 * pen);
            // Reset so the captured graph replays identically.
            atomicExch(&g_loss_acc, 0ULL);
            atomicExch(&g_score_acc, 0);
            __threadfence();
            atomicExch(&g_done, 0u);
        }
    }
}

// ---------------------------------------------------------------------------
extern "C" void kernel_launch(void* const* d_in, const int* in_sizes, int n_in,
                              void* d_out, int out_size) {
    const float* preds    = (const float*)d_in[0];
    const int*   labels_w = (const int*)d_in[1];
    const float* imu      = (const float*)d_in[2];
    const int B = in_sizes[1];                     // 32768

    const int physCtas = (B + NW - 1) / NW;        // 4096
    const int taskCtas = (B + 7) / 8;              // 4096
    fused_kernel<<<physCtas + taskCtas, 128>>>(imu, preds, labels_w,
                                               (float*)d_out, B, physCtas);
}

// round 17
// speedup vs baseline: 1.5866x; 1.0321x over previous
#include <cuda_runtime.h>
#include <math.h>

// Problem shape: B=32768, T=512, channels=3, C=128 logits.
#define T_LEN 512
#define WIN_BYTES (T_LEN * 3 * 4)       // 6144
#define NW 16                           // windows per physics CTA
#define NSTG 3                          // TMA pipeline stages
#define STG_FLTS (T_LEN * 3 + 16)       // stage stride (floats), halo pad
#define LOSS_SCALE 4194304.0f           // 2^22 fixed point => deterministic sum

__device__ unsigned long long g_loss_acc = 0ULL;
__device__ int                g_score_acc = 0;
__device__ unsigned int       g_done = 0u;

__device__ __forceinline__ unsigned smem_u32(const void* p) {
    unsigned r;
    asm("{ .reg .u64 t; cvta.to.shared.u64 t, %1; cvt.u32.u64 %0, t; }"
        : "=r"(r) : "l"(p));
    return r;
}

__device__ __forceinline__ void tma_issue(unsigned mb, unsigned sdst, const float* src) {
    asm volatile("mbarrier.arrive.expect_tx.shared.b64 _, [%0], %1;"
                 :: "r"(mb), "r"((unsigned)WIN_BYTES) : "memory");
    asm volatile(
        "cp.async.bulk.shared::cluster.global.mbarrier::complete_tx::bytes"
        " [%0], [%1], %2, [%3];"
        :: "r"(sdst), "l"(src), "r"((unsigned)WIN_BYTES), "r"(mb) : "memory");
}

__device__ __forceinline__ void mbar_wait(unsigned mb, unsigned ph) {
    asm volatile(
        "{\n\t.reg .pred P;\n\t"
        "W%=:\n\t"
        "mbarrier.try_wait.parity.acquire.cta.shared::cta.b64 P, [%0], %1, 0x989680;\n\t"
        "@P bra D%=;\n\t"
        "bra W%=;\n\t"
        "D%=:\n\t}"
        :: "r"(mb), "r"(ph) : "memory");
}

// ---- packed f32x2 helpers (sm_103a) ----
__device__ __forceinline__ unsigned long long pk2(float a, float b) {
    unsigned long long r;
    asm("mov.b64 %0, {%1, %2};" : "=l"(r)
        : "r"(__float_as_uint(a)), "r"(__float_as_uint(b)));
    return r;
}
__device__ __forceinline__ void unpk2(unsigned long long v, float& a, float& b) {
    unsigned x, y;
    asm("mov.b64 {%0, %1}, %2;" : "=r"(x), "=r"(y) : "l"(v));
    a = __uint_as_float(x); b = __uint_as_float(y);
}
__device__ __forceinline__ unsigned long long add2(unsigned long long a, unsigned long long b) {
    unsigned long long r;
    asm("add.rn.f32x2 %0, %1, %2;" : "=l"(r) : "l"(a), "l"(b));
    return r;
}
__device__ __forceinline__ unsigned long long fma2(unsigned long long a, unsigned long long b,
                                                   unsigned long long c) {
    unsigned long long r;
    asm("fma.rn.f32x2 %0, %1, %2, %3;" : "=l"(r) : "l"(a), "l"(b), "l"(c));
    return r;
}

// tid0 score finalize for one window (integer partials in ri, tv/X in regs).
__device__ __forceinline__ int window_score(const int ri[2][4],
                                            float tv, float X0, float X1, float X2) {
    int paT = ri[0][0] + ri[0][1] + ri[0][2] + ri[0][3];
    int pbT = ri[1][0] + ri[1][1] + ri[1][2] + ri[1][3];
    int cc0 = paT & 1023, cc1 = (paT >> 10) & 1023, cc2 = (paT >> 20) & 1023;
    int zcc = pbT & 0xffff, jcc = pbT >> 16;

    bool reject = tv < 0.005f;
    reject |= (X0 >= 0.5f) && ((float)cc0 * (1.0f / 512.0f) > 0.2f);
    reject |= (X1 >= 0.5f) && ((float)cc1 * (1.0f / 512.0f) > 0.2f);
    reject |= (X2 >= 0.5f) && ((float)cc2 * (1.0f / 512.0f) > 0.2f);
    reject |= (jcc >= 77);              // js[1447]>5000 <=> count(>5000) >= 77

    float s1v = tv > 10.0f ? 90.0f
              : (tv > 2.0f ? 80.0f : (tv > 0.5f ? 70.0f : 58.0f));
    float zcr = (float)zcc * (1.0f / 512.0f);
    float s2v = zcr > 0.15f ? 85.0f : (zcr > 0.07f ? 70.0f : 55.0f);
    return reject ? 0 : (int)floorf((s1v + s2v) * 0.5f);
}

__global__ __launch_bounds__(128) void fused_kernel(
    const float* __restrict__ imu,
    const float* __restrict__ preds,
    const int*   __restrict__ labels_w,   // raw 32-bit view of labels buffer
    float*       __restrict__ out,
    int B, int physCtas)
{
    __shared__ __align__(16) float sbuf[NSTG][STG_FLTS];
    __shared__ __align__(8) unsigned long long mbar[NSTG];
    __shared__ float redf[2][7][4];       // [window parity][field][warp]
    __shared__ int   redi[2][2][4];
    __shared__ float lsh[4];

    const int tid  = threadIdx.x;
    const int warp = tid >> 5;
    const int lane = tid & 31;
    const unsigned FULL = 0xffffffffu;

    if ((int)blockIdx.x < physCtas) {
        // ===== PHYSICS: NW windows/CTA, 3-stage TMA ring, 1 bar/window =====
        const int b0  = blockIdx.x * NW;
        const int nwl = (B - b0 < NW) ? (B - b0) : NW;
        const float* gsrc = imu + (size_t)b0 * (T_LEN * 3);

        unsigned mbA[NSTG], sdA[NSTG];
#pragma unroll
        for (int k = 0; k < NSTG; k++) {
            mbA[k] = smem_u32(&mbar[k]);
            sdA[k] = smem_u32(sbuf[k]);
        }
        if (tid == 0) {
#pragma unroll
            for (int k = 0; k < NSTG; k++)
                asm volatile("mbarrier.init.shared.b64 [%0], 1;"
                             :: "r"(mbA[k]) : "memory");
        }
        __syncthreads();
        if (tid == 0) {
            const int npro = nwl < NSTG ? nwl : NSTG;
            for (int k = 0; k < npro; k++)
                tma_issue(mbA[k], sdA[k], gsrc + (size_t)k * (T_LEN * 3));
        }

        int scoreSum = 0;                          // tid0 only
        float tvP = 0.f, XP0 = 0.f, XP1 = 0.f, XP2 = 0.f;
        int st = 0, ph = 0;
        const unsigned long long NEG2 = pk2(-2.0f, -2.0f);

#pragma unroll 1
        for (int w = 0; w < nwl; w++) {
            mbar_wait(mbA[st], (unsigned)ph);

            // Own timesteps 4*tid..4*tid+3 (+4 halo): 6 conflict-free LDS.128.
            float f[24];
            {
                const float4* sv =
                    reinterpret_cast<const float4*>(sbuf[st] + 12 * tid);
#pragma unroll
                for (int j = 0; j < 6; j++)
                    *reinterpret_cast<float4*>(f + 4 * j) = sv[j];
            }

            // ---- Pass 1 (packed): sums + sum-of-squares; scalar max|w| ----
            // pair j = (f[2j], f[2j+1]); channel pattern has period 3.
            unsigned long long A0 = 0, A1 = 0, A2 = 0, Q = 0;
#pragma unroll
            for (int g = 0; g < 2; g++) {
                unsigned long long p0 = pk2(f[6 * g * 1 + 0 + 0], f[6 * g + 1]);
                unsigned long long p1 = pk2(f[6 * g + 2], f[6 * g + 3]);
                unsigned long long p2 = pk2(f[6 * g + 4], f[6 * g + 5]);
                A0 = (g == 0) ? p0 : add2(A0, p0);
                A1 = (g == 0) ? p1 : add2(A1, p1);
                A2 = (g == 0) ? p2 : add2(A2, p2);
                Q = fma2(p0, p0, Q); Q = fma2(p1, p1, Q); Q = fma2(p2, p2, Q);
            }
            float a0x, a0y, a1x, a1y, a2x, a2y, qx, qy;
            unpk2(A0, a0x, a0y); unpk2(A1, a1x, a1y); unpk2(A2, a2x, a2y);
            unpk2(Q, qx, qy);
            float s0 = a0x + a1y, s1 = a0y + a2x, s2 = a1x + a2y, q = qx + qy;

            float M0 = 0.f, M1 = 0.f, M2 = 0.f;
#pragma unroll
            for (int i = 0; i < 4; i++) {          // FMNMX folds |src|
                M0 = fmaxf(M0, fabsf(f[3 * i]));
                M1 = fmaxf(M1, fabsf(f[3 * i + 1]));
                M2 = fmaxf(M2, fabsf(f[3 * i + 2]));
            }

            // Warp reduce: (s0,s1),(s2,q) packed; maxes via HW redux.
            unsigned long long SA = pk2(s0, s1), SB = pk2(s2, q);
#pragma unroll
            for (int o = 16; o; o >>= 1) {
                SA = add2(SA, __shfl_xor_sync(FULL, SA, o));
                SB = add2(SB, __shfl_xor_sync(FULL, SB, o));
            }
            M0 = __uint_as_float(__reduce_max_sync(FULL, __float_as_uint(M0)));
            M1 = __uint_as_float(__reduce_max_sync(FULL, __float_as_uint(M1)));
            M2 = __uint_as_float(__reduce_max_sync(FULL, __float_as_uint(M2)));

            const int par = w & 1;
            if (lane == 0) {
                unpk2(SA, s0, s1); unpk2(SB, s2, q);
                redf[par][0][warp] = s0; redf[par][1][warp] = s1;
                redf[par][2][warp] = s2; redf[par][3][warp] = q;
                redf[par][4][warp] = M0; redf[par][5][warp] = M1;
                redf[par][6][warp] = M2;
            }
            __syncthreads();   // redf[par] ready; stage st fully consumed;
                               // redi[par^1] (window w-1) complete in all warps

            if (tid == 0) {
                if (w > 0)     // finalize window w-1 (off critical path)
                    scoreSum += window_score(redi[par ^ 1], tvP, XP0, XP1, XP2);
                if (w + NSTG < nwl)
                    tma_issue(mbA[st], sdA[st],
                              gsrc + (size_t)(w + NSTG) * (T_LEN * 3));
            }

            const float m0 = (redf[par][0][0] + redf[par][0][1] + redf[par][0][2] + redf[par][0][3]) * (1.0f / 512.0f);
            const float m1 = (redf[par][1][0] + redf[par][1][1] + redf[par][1][2] + redf[par][1][3]) * (1.0f / 512.0f);
            const float m2 = (redf[par][2][0] + redf[par][2][1] + redf[par][2][2] + redf[par][2][3]) * (1.0f / 512.0f);
            const float qT =  redf[par][3][0] + redf[par][3][1] + redf[par][3][2] + redf[par][3][3];
            const float X0 = fmaxf(fmaxf(redf[par][4][0], redf[par][4][1]), fmaxf(redf[par][4][2], redf[par][4][3]));
            const float X1 = fmaxf(fmaxf(redf[par][5][0], redf[par][5][1]), fmaxf(redf[par][5][2], redf[par][5][3]));
            const float X2 = fmaxf(fmaxf(redf[par][6][0], redf[par][6][1]), fmaxf(redf[par][6][2], redf[par][6][3]));
            // tv = sum(w^2)/n - sum_c m_c^2 (n*m^2 << sum w^2: no cancellation).
            const float tv = qT * (1.0f / 512.0f) - (m0 * m0 + m1 * m1 + m2 * m2);
            if (tid == 0) { tvP = tv; XP0 = X0; XP1 = X1; XP2 = X2; }

            // ---- Pass 2: zc (scalar), jerk (packed), at_max (rare) ----
            int zc = 0, jc = 0, c0 = 0, c1 = 0, c2 = 0;
            const bool notLast = (tid != 127);
#pragma unroll
            for (int i = 0; i < 4; i++) {          // zc pairs t < 511
                if (notLast || i < 3) {
                    float d0 = f[3 * i] - m0;
                    float e0 = f[3 * i + 3] - m0;  // i==3 -> halo f[12]
                    zc += (d0 * e0 < 0.0f);
                }
            }
            if (notLast) {                         // jerk valid t < 508
#pragma unroll
                for (int j = 0; j < 6; j++) {
                    // elements 2j,2j+1: stencil +6/+12 floats = +3/+6 pairs
                    unsigned long long pa_ = pk2(f[2 * j],      f[2 * j + 1]);
                    unsigned long long pb_ = pk2(f[2 * j + 6],  f[2 * j + 7]);
                    unsigned long long pc_ = pk2(f[2 * j + 12], f[2 * j + 13]);
                    unsigned long long jv = fma2(pb_, NEG2, add2(pa_, pc_));
                    float jx, jy; unpk2(jv, jx, jy);
                    jc += (fabsf(jx) > 8.0f);      // == |jerk| > 5000
                    jc += (fabsf(jy) > 8.0f);
                }
            }
            const bool needAM = (X0 >= 0.5f) || (X1 >= 0.5f) || (X2 >= 0.5f);
            if (needAM) {                          // CTA-uniform, ~0.1%
#pragma unroll
                for (int i = 0; i < 4; i++) {
                    c0 += (fabsf(fabsf(f[3 * i])     - X0) < 0.01f);
                    c1 += (fabsf(fabsf(f[3 * i + 1]) - X1) < 0.01f);
                    c2 += (fabsf(fabsf(f[3 * i + 2]) - X2) < 0.01f);
                }
            }
            int pa = c0 | (c1 << 10) | (c2 << 20); // counts <= 512 each
            int pb = zc | (jc << 16);              // zc <= 511, jc <= 1524
            pa = (int)__reduce_add_sync(FULL, (unsigned)pa);
            pb = (int)__reduce_add_sync(FULL, (unsigned)pb);
            if (lane == 0) { redi[par][0][warp] = pa; redi[par][1][warp] = pb; }

            st++; if (st == NSTG) { st = 0; ph ^= 1; }
        }
        __syncthreads();
        if (tid == 0) {
            if (nwl > 0)
                scoreSum += window_score(redi[(nwl - 1) & 1], tvP, XP0, XP1, XP2);
            if (scoreSum) atomicAdd(&g_score_acc, scoreSum);
        }
    } else {
        // ============ TASK LOSS: 2 rows per warp, 8 rows/CTA ============
        const int base = ((int)blockIdx.x - physCtas) * 8 + warp;

        // Labels dtype detect (first 128 words; L2-hit after first CTA):
        // int64 LE => all odd words (high halves of values < 128) are zero.
        int aa = labels_w[2 * lane + 1] | labels_w[2 * (lane + 32) + 1];
        aa = (int)__reduce_add_sync(FULL, (unsigned)aa);
        const int is64 = (aa == 0);

        float lossSum = 0.f;
#pragma unroll
        for (int r = 0; r < 2; r++) {
            const int row = base + 4 * r;
            if (row < B) {
                const float4* p4 =
                    reinterpret_cast<const float4*>(preds + (size_t)row * 128);
                float4 vv = p4[lane];
                float mx = fmaxf(fmaxf(vv.x, vv.y), fmaxf(vv.z, vv.w));
#pragma unroll
                for (int o = 16; o; o >>= 1)
                    mx = fmaxf(mx, __shfl_xor_sync(FULL, mx, o));
                float sum = __expf(vv.x - mx) + __expf(vv.y - mx) +
                            __expf(vv.z - mx) + __expf(vv.w - mx);
#pragma unroll
                for (int o = 16; o; o >>= 1)
                    sum += __shfl_xor_sync(FULL, sum, o);
                if (lane == 0) {
                    int lbl = is64 ? labels_w[2 * (size_t)row] : labels_w[row];
                    float pl = preds[(size_t)row * 128 + lbl];
                    lossSum += __logf(sum) + mx - pl;   // -(pl - logsumexp)
                }
            }
        }
        if (lane == 0) lsh[warp] = lossSum;
        __syncthreads();
        if (tid == 0) {
            unsigned long long acc = 0ULL;
#pragma unroll
            for (int j = 0; j < 4; j++)
                acc += (unsigned long long)llrintf(lsh[j] * LOSS_SCALE);
            atomicAdd(&g_loss_acc, acc);
        }
    }

    // ============ Last-CTA finalize (deterministic: integer sums) ============
    if (tid == 0) {
        __threadfence();
        unsigned int done = atomicAdd(&g_done, 1u);
        if (done == gridDim.x - 1) {
            unsigned long long L = atomicAdd(&g_loss_acc, 0ULL);
            int S = atomicAdd(&g_score_acc, 0);
            double task = (double)L / ((double)LOSS_SCALE * (double)B);
            double pen  = 1.0 - (double)S / (100.0 * (double)B);
            out[0] = (float)(task + 0.3 * pen);
            // Reset so the captured graph replays identically.
            atomicExch(&g_loss_acc, 0ULL);
            atomicExch(&g_score_acc, 0);
            __threadfence();
            atomicExch(&g_done, 0u);
        }
    }
}

// ---------------------------------------------------------------------------
extern "C" void kernel_launch(void* const* d_in, const int* in_sizes, int n_in,
                              void* d_out, int out_size) {
    const float* preds    = (const float*)d_in[0];
    const int*   labels_w = (const int*)d_in[1];
    const float* imu      = (const float*)d_in[2];
    const int B = in_sizes[1];                     // 32768

    const int physCtas = (B + NW - 1) / NW;        // 2048
    const int taskCtas = (B + 7) / 8;              // 4096
    fused_kernel<<<physCtas + taskCtas, 128>>>(imu, preds, labels_w,
                                               (float*)d_out, B, physCtas);
}